// round 10
// baseline (speedup 1.0000x reference)
#include <cuda_runtime.h>
#include <cstdint>

// Problem constants
#define B    32
#define H    768
#define W    768
#define IMG  (H * W)               // 589824
#define NPIX (B * IMG)             // 18874368
#define RSM_K 35

#define NG   (W / 32)              // 24 column groups of 32
#define CHUNKS 8
#define CHUNK_ROWS (H / CHUNKS)    // 96

// Bitmask: bit c of g_bits[(b*NG+g)*H + y] = mask[b][y][32g+c]  (y-contiguous)
__device__ uint32_t g_bits[B * NG * H];

// Intermediate: one byte per pixel.
//   bits 0-5 : vertical 35-window popcount (0..35)
//   bit  6   : center mask bit
//   bit  7   : vertical 31-window "any" flag
__device__ uint8_t g_packed[NPIX];

// ---------------------------------------------------------------------------
// Pass 1a: float mask -> bitmask, transposed layout. Pure streaming.
// Thread handles 32 consecutive floats of one row. grid: NPIX/32/256 = 2304.
// ---------------------------------------------------------------------------
__global__ __launch_bounds__(256) void pass1a_bits(const float* __restrict__ masks) {
    const int gid = blockIdx.x * 256 + threadIdx.x;   // 0 .. B*NG*H-1
    const int y   = gid % H;
    const int bg  = gid / H;                          // b*NG + g
    const int b   = bg / NG;
    const int g   = bg - b * NG;

    const float4* src = (const float4*)(masks + (size_t)b * IMG + (size_t)y * W + g * 32);

    uint32_t bits = 0;
    #pragma unroll
    for (int i = 0; i < 8; ++i) {
        const float4 v = src[i];
        bits |= (uint32_t)(v.x > 0.5f) << (i * 4);
        bits |= (uint32_t)(v.y > 0.5f) << (i * 4 + 1);
        bits |= (uint32_t)(v.z > 0.5f) << (i * 4 + 2);
        bits |= (uint32_t)(v.w > 0.5f) << (i * 4 + 3);
    }
    g_bits[gid] = bits;
}

// ---------------------------------------------------------------------------
// Pass 1b: vertical sliding bit-window over the bitmask.
// Warp owns one (b, g, chunk); lane = column within group. Per row, all lanes
// read the same word (broadcast, cache-resident) and extract their bit.
// grid: B * 3 * CHUNKS blocks of 256 (8 warps; warp w -> group gb*8+w).
// ---------------------------------------------------------------------------
__global__ __launch_bounds__(256) void pass1b_vertical() {
    const int lane  = threadIdx.x & 31;
    const int w     = threadIdx.x >> 5;
    const int chunk = blockIdx.x & (CHUNKS - 1);
    int tmp         = blockIdx.x >> 3;          // log2(CHUNKS)=3
    const int gb    = tmp % 3;
    const int b     = tmp / 3;
    const int g     = gb * 8 + w;
    const int r0    = chunk * CHUNK_ROWS;

    const uint32_t* bm = g_bits + (size_t)(b * NG + g) * H;
    uint8_t* obase = g_packed + (size_t)b * IMG + g * 32 + lane;

    const uint64_t M35 = (1ULL << 35) - 1;
    const uint64_t M31 = (1ULL << 31) - 1;

    uint64_t win = 0;

    // Prologue: rows r0-17 .. r0+16 (34 rows)
    #pragma unroll 1
    for (int pb = 0; pb < 34; pb += 17) {
        uint32_t wv[17];
        #pragma unroll
        for (int i = 0; i < 17; ++i) {
            const int t = r0 - 17 + pb + i;     // t <= r0+16 <= 688 < H
            wv[i] = (t >= 0) ? bm[t] : 0u;
        }
        #pragma unroll
        for (int i = 0; i < 17; ++i)
            win = (win << 1) | (uint64_t)((wv[i] >> lane) & 1u);
    }

    // Emit loop: batches of 8 rows
    #pragma unroll 1
    for (int yb = 0; yb < CHUNK_ROWS; yb += 8) {
        uint32_t wv[8];
        #pragma unroll
        for (int i = 0; i < 8; ++i) {
            const int t = r0 + yb + i + 17;
            wv[i] = (t < H) ? bm[t] : 0u;
        }
        #pragma unroll
        for (int i = 0; i < 8; ++i) {
            win = (win << 1) | (uint64_t)((wv[i] >> lane) & 1u);
            const uint32_t cnt    = (uint32_t)__popcll(win & M35);
            const uint32_t center = (uint32_t)((win >> 17) & 1ULL);
            const uint32_t flag   = (((win >> 2) & M31) != 0ULL) ? 0x80u : 0u;
            const int y = r0 + yb + i;
            obase[(size_t)y * W] = (uint8_t)(cnt | (center << 6) | flag);
        }
    }
}

// ---------------------------------------------------------------------------
// Pass 2: per-row horizontal windows via one fused prefix sum.
// 192 threads per block, one row per block, 4 outputs per thread.
// (Measured-best variant; unchanged.)
// ---------------------------------------------------------------------------
#define PAD 20

__global__ __launch_bounds__(192) void pass2_horizontal(float* __restrict__ out_rsm,
                                                        float* __restrict__ out_pfm) {
    __shared__ __align__(16) uint32_t sPp[PAD + W + 17];  // padded fused prefix
    __shared__ uint32_t sWarp[6];

    const int tid  = threadIdx.x;
    const int lane = tid & 31;
    const int wid  = tid >> 5;
    const int row  = blockIdx.x;        // b*H + y
    const int x0   = tid * 4;

    // One u32 = this thread's 4 packed bytes (byte j -> x = x0 + j)
    const uint32_t w = ((const uint32_t*)(g_packed + (size_t)row * W))[tid];

    if (tid < PAD) sPp[tid] = 0;

    // Unpack: v = (cnt << 16) | flag
    uint32_t v0, v1, v2, v3;
    {
        uint32_t c0 = (w      ) & 63u, f0 = (w >> 7 ) & 1u;
        uint32_t c1 = (w >> 8 ) & 63u, f1 = (w >> 15) & 1u;
        uint32_t c2 = (w >> 16) & 63u, f2 = (w >> 23) & 1u;
        uint32_t c3 = (w >> 24) & 63u, f3 = (w >> 31);
        v0 = c0 * 65536u + f0;
        v1 = c1 * 65536u + f1;
        v2 = c2 * 65536u + f2;
        v3 = c3 * 65536u + f3;
    }
    const uint32_t s0 = v0;
    const uint32_t s1 = s0 + v1;
    const uint32_t s2 = s1 + v2;
    const uint32_t s3 = s2 + v3;

    // Warp inclusive scan of per-thread totals
    uint32_t sc = s3;
    #pragma unroll
    for (int d = 1; d < 32; d <<= 1) {
        uint32_t y = __shfl_up_sync(0xFFFFFFFFu, sc, d);
        if (lane >= d) sc += y;
    }
    if (lane == 31) sWarp[wid] = sc;
    __syncthreads();
    if (tid == 0) {
        uint32_t acc = sWarp[0];
        #pragma unroll
        for (int i = 1; i < 6; ++i) { acc += sWarp[i]; sWarp[i] = acc; }
    }
    __syncthreads();

    const uint32_t excl = (sc - s3) + (wid ? sWarp[wid - 1] : 0u);

    // Inclusive prefix at x0..x0+3 (vector STS)
    {
        uint4 p;
        p.x = excl + s0;
        p.y = excl + s1;
        p.z = excl + s2;
        p.w = excl + s3;
        *(uint4*)&sPp[PAD + x0] = p;
    }
    // Right pad: replicate row total P[W-1]
    if (tid < 17) sPp[PAD + W + tid] = sWarp[5];
    __syncthreads();

    // Window reads (all indices pre-shifted by PAD=20):
    //   lo35_j = sPp[x0 + j + 2]   (x - 18 + PAD)
    //   lo31_j = sPp[x0 + j + 4]   (x - 16 + PAD)
    //   hi31_j = sPp[x0 + j + 35]  (x + 15 + PAD, clamp via right pad)
    //   hi35_j = sPp[x0 + j + 37]  (x + 17 + PAD, clamp via right pad)
    const uint2 A01 = *(const uint2*)&sPp[x0 + 2];   // [x0+2, x0+3]
    const uint4 A25 = *(const uint4*)&sPp[x0 + 4];   // [x0+4 .. x0+7]
    const uint32_t b35 = sPp[x0 + 35];
    const uint4 B69 = *(const uint4*)&sPp[x0 + 36];  // [x0+36 .. x0+39]
    const uint32_t b40 = sPp[x0 + 40];

    const float inv = 1.0f / (float)(RSM_K * RSM_K);

    // hi - lo has no cross-field borrow (both fields monotone):
    //   sum35 = (hi35 - lo35) >> 16,  f31 = (hi31 - lo31) & 0xFFFF
    uint32_t d35_0 = B69.y - A01.x;
    uint32_t d35_1 = B69.z - A01.y;
    uint32_t d35_2 = B69.w - A25.x;
    uint32_t d35_3 = b40   - A25.y;

    uint32_t f31_0 = (b35   - A25.x) & 0xFFFFu;
    uint32_t f31_1 = (B69.x - A25.y) & 0xFFFFu;
    uint32_t f31_2 = (B69.y - A25.z) & 0xFFFFu;
    uint32_t f31_3 = (B69.z - A25.w) & 0xFFFFu;

    float4 rsm4;
    rsm4.x = (float)(d35_0 >> 16) * inv;
    rsm4.y = (float)(d35_1 >> 16) * inv;
    rsm4.z = (float)(d35_2 >> 16) * inv;
    rsm4.w = (float)(d35_3 >> 16) * inv;

    // pfm = center ? 1 : (f31 ? 0 : 2) == center + 2*(f31==0)
    float4 pfm4;
    pfm4.x = (float)(((w >> 6)  & 1u) + ((f31_0 == 0u) ? 2u : 0u));
    pfm4.y = (float)(((w >> 14) & 1u) + ((f31_1 == 0u) ? 2u : 0u));
    pfm4.z = (float)(((w >> 22) & 1u) + ((f31_2 == 0u) ? 2u : 0u));
    pfm4.w = (float)(((w >> 30) & 1u) + ((f31_3 == 0u) ? 2u : 0u));

    *(float4*)(out_rsm + (size_t)row * W + x0) = rsm4;
    *(float4*)(out_pfm + (size_t)row * W + x0) = pfm4;
}

// ---------------------------------------------------------------------------
extern "C" void kernel_launch(void* const* d_in, const int* in_sizes, int n_in,
                              void* d_out, int out_size) {
    const float* masks = (const float*)d_in[0];
    float* out = (float*)d_out;

    pass1a_bits<<<(B * NG * H) / 256, 256>>>(masks);
    pass1b_vertical<<<B * 3 * CHUNKS, 256>>>();
    pass2_horizontal<<<B * H, 192>>>(out, out + NPIX);
}

// round 11
// speedup vs baseline: 1.2247x; 1.2247x over previous
#include <cuda_runtime.h>
#include <cstdint>

// Problem constants
#define B    32
#define H    768
#define W    768
#define IMG  (H * W)               // 589824
#define NPIX (B * IMG)             // 18874368
#define RSM_K 35

// Pass-1 row chunking: 8 chunks of 96 rows (+17/+16 halo, amp 1.35)
#define CHUNKS 8
#define CHUNK_ROWS (H / CHUNKS)    // 96

// Intermediate: one byte per pixel.
//   bits 0-5 : vertical 35-window popcount (0..35)
//   bit  6   : center mask bit
//   bit  7   : vertical 31-window "any" flag
__device__ uint8_t g_packed[NPIX];

// ---------------------------------------------------------------------------
// Pass 1: vertical sliding bit-window per column, explicit load batching for
// MLP. grid: B * 3 * CHUNKS = 768 blocks of 256 threads.
// ---------------------------------------------------------------------------
__global__ __launch_bounds__(256) void pass1_vertical(const float* __restrict__ masks) {
    const int tid   = threadIdx.x;
    const int chunk = blockIdx.x & (CHUNKS - 1);
    int tmp         = blockIdx.x >> 3;          // log2(CHUNKS)=3
    const int xb    = tmp % 3;
    const int b     = tmp / 3;
    const int x     = xb * 256 + tid;

    const int r0 = chunk * CHUNK_ROWS;

    const float*  ibase = masks    + (size_t)b * IMG + x;
    uint8_t*      obase = g_packed + (size_t)b * IMG + x;

    const uint64_t M35 = (1ULL << 35) - 1;
    const uint64_t M31 = (1ULL << 31) - 1;

    uint64_t bits = 0;

    // Prologue: rows r0-17 .. r0+16 (34 rows), two batches of 17 loads
    #pragma unroll 1
    for (int pb = 0; pb < 34; pb += 17) {
        float fv[17];
        #pragma unroll
        for (int i = 0; i < 17; ++i) {
            const int t = r0 - 17 + pb + i;     // t <= r0+16 <= 688 < H
            fv[i] = 0.0f;
            if (t >= 0) fv[i] = ibase[(size_t)t * W];
        }
        #pragma unroll
        for (int i = 0; i < 17; ++i)
            bits = (bits << 1) | (uint64_t)(fv[i] > 0.5f);
    }

    // Emit loop: batches of 8 rows; 8 outstanding LDGs per warp per batch.
    #pragma unroll 1
    for (int yb = 0; yb < CHUNK_ROWS; yb += 8) {
        float fv[8];
        #pragma unroll
        for (int i = 0; i < 8; ++i) {
            const int t = r0 + yb + i + 17;
            fv[i] = 0.0f;
            if (t < H) fv[i] = ibase[(size_t)t * W];
        }
        #pragma unroll
        for (int i = 0; i < 8; ++i) {
            bits = (bits << 1) | (uint64_t)(fv[i] > 0.5f);
            const int y = r0 + yb + i;
            // bit k of 'bits' = row (current_t - k)
            uint32_t cnt    = (uint32_t)__popcll(bits & M35);          // rows y-17..y+17
            uint32_t center = (uint32_t)((bits >> 17) & 1ULL);         // row y
            uint32_t flag   = (((bits >> 2) & M31) != 0ULL) ? 1u : 0u; // rows y-15..y+15
            obase[(size_t)y * W] = (uint8_t)(cnt | (center << 6) | (flag << 7));
        }
    }
}

// ---------------------------------------------------------------------------
// Pass 2: per-row horizontal windows via one fused prefix sum.
// 192 threads per block, one row per block, 4 outputs per thread.
// (Measured-best variant; outputs use __stcs to keep L2 for the intermediate.)
// ---------------------------------------------------------------------------
#define PAD 20

__global__ __launch_bounds__(192) void pass2_horizontal(float* __restrict__ out_rsm,
                                                        float* __restrict__ out_pfm) {
    __shared__ __align__(16) uint32_t sPp[PAD + W + 17];  // padded fused prefix
    __shared__ uint32_t sWarp[6];

    const int tid  = threadIdx.x;
    const int lane = tid & 31;
    const int wid  = tid >> 5;
    const int row  = blockIdx.x;        // b*H + y
    const int x0   = tid * 4;

    // One u32 = this thread's 4 packed bytes (byte j -> x = x0 + j)
    const uint32_t w = ((const uint32_t*)(g_packed + (size_t)row * W))[tid];

    if (tid < PAD) sPp[tid] = 0;

    // Unpack: v = (cnt << 16) | flag
    uint32_t v0, v1, v2, v3;
    {
        uint32_t c0 = (w      ) & 63u, f0 = (w >> 7 ) & 1u;
        uint32_t c1 = (w >> 8 ) & 63u, f1 = (w >> 15) & 1u;
        uint32_t c2 = (w >> 16) & 63u, f2 = (w >> 23) & 1u;
        uint32_t c3 = (w >> 24) & 63u, f3 = (w >> 31);
        v0 = c0 * 65536u + f0;
        v1 = c1 * 65536u + f1;
        v2 = c2 * 65536u + f2;
        v3 = c3 * 65536u + f3;
    }
    const uint32_t s0 = v0;
    const uint32_t s1 = s0 + v1;
    const uint32_t s2 = s1 + v2;
    const uint32_t s3 = s2 + v3;

    // Warp inclusive scan of per-thread totals
    uint32_t sc = s3;
    #pragma unroll
    for (int d = 1; d < 32; d <<= 1) {
        uint32_t y = __shfl_up_sync(0xFFFFFFFFu, sc, d);
        if (lane >= d) sc += y;
    }
    if (lane == 31) sWarp[wid] = sc;
    __syncthreads();
    if (tid == 0) {
        uint32_t acc = sWarp[0];
        #pragma unroll
        for (int i = 1; i < 6; ++i) { acc += sWarp[i]; sWarp[i] = acc; }
    }
    __syncthreads();

    const uint32_t excl = (sc - s3) + (wid ? sWarp[wid - 1] : 0u);

    // Inclusive prefix at x0..x0+3 (vector STS)
    {
        uint4 p;
        p.x = excl + s0;
        p.y = excl + s1;
        p.z = excl + s2;
        p.w = excl + s3;
        *(uint4*)&sPp[PAD + x0] = p;
    }
    // Right pad: replicate row total P[W-1]
    if (tid < 17) sPp[PAD + W + tid] = sWarp[5];
    __syncthreads();

    // Window reads (all indices pre-shifted by PAD=20):
    //   lo35_j = sPp[x0 + j + 2]   (x - 18 + PAD)
    //   lo31_j = sPp[x0 + j + 4]   (x - 16 + PAD)
    //   hi31_j = sPp[x0 + j + 35]  (x + 15 + PAD, clamp via right pad)
    //   hi35_j = sPp[x0 + j + 37]  (x + 17 + PAD, clamp via right pad)
    const uint2 A01 = *(const uint2*)&sPp[x0 + 2];   // [x0+2, x0+3]
    const uint4 A25 = *(const uint4*)&sPp[x0 + 4];   // [x0+4 .. x0+7]
    const uint32_t b35 = sPp[x0 + 35];
    const uint4 B69 = *(const uint4*)&sPp[x0 + 36];  // [x0+36 .. x0+39]
    const uint32_t b40 = sPp[x0 + 40];

    const float inv = 1.0f / (float)(RSM_K * RSM_K);

    // hi - lo has no cross-field borrow (both fields monotone):
    //   sum35 = (hi35 - lo35) >> 16,  f31 = (hi31 - lo31) & 0xFFFF
    uint32_t d35_0 = B69.y - A01.x;
    uint32_t d35_1 = B69.z - A01.y;
    uint32_t d35_2 = B69.w - A25.x;
    uint32_t d35_3 = b40   - A25.y;

    uint32_t f31_0 = (b35   - A25.x) & 0xFFFFu;
    uint32_t f31_1 = (B69.x - A25.y) & 0xFFFFu;
    uint32_t f31_2 = (B69.y - A25.z) & 0xFFFFu;
    uint32_t f31_3 = (B69.z - A25.w) & 0xFFFFu;

    float4 rsm4;
    rsm4.x = (float)(d35_0 >> 16) * inv;
    rsm4.y = (float)(d35_1 >> 16) * inv;
    rsm4.z = (float)(d35_2 >> 16) * inv;
    rsm4.w = (float)(d35_3 >> 16) * inv;

    // pfm = center ? 1 : (f31 ? 0 : 2) == center + 2*(f31==0)
    float4 pfm4;
    pfm4.x = (float)(((w >> 6)  & 1u) + ((f31_0 == 0u) ? 2u : 0u));
    pfm4.y = (float)(((w >> 14) & 1u) + ((f31_1 == 0u) ? 2u : 0u));
    pfm4.z = (float)(((w >> 22) & 1u) + ((f31_2 == 0u) ? 2u : 0u));
    pfm4.w = (float)(((w >> 30) & 1u) + ((f31_3 == 0u) ? 2u : 0u));

    // Streaming stores: outputs are never re-read; keep L2 for g_packed.
    __stcs((float4*)(out_rsm + (size_t)row * W + x0), rsm4);
    __stcs((float4*)(out_pfm + (size_t)row * W + x0), pfm4);
}

// ---------------------------------------------------------------------------
extern "C" void kernel_launch(void* const* d_in, const int* in_sizes, int n_in,
                              void* d_out, int out_size) {
    const float* masks = (const float*)d_in[0];
    float* out = (float*)d_out;

    pass1_vertical<<<B * 3 * CHUNKS, 256>>>(masks);
    pass2_horizontal<<<B * H, 192>>>(out, out + NPIX);
}